// round 15
// baseline (speedup 1.0000x reference)
#include <cuda_runtime.h>
#include <cuda_fp16.h>
#include <cstdint>

#define B_ 64
#define F_ 4
#define M_ 4096
#define D_ 1024
#define ITERS_ 15
#define NCTA_ 128
#define NHALF_ (B_ * D_ / 2)

// ---------------- device scratch ----------------
__device__ __half   g_Ch[F_ * M_ * D_];      // codebooks fp16 +-1, [f][m][d]
__device__ unsigned g_Cb[F_ * D_ * 128];     // bitpacked columns: bit j of [f][d][w] = sign(C[f][w*32+j][d])
__device__ __half   g_G[F_ * D_ * D_];       // (C^T C)/2 fp16, [f][d1][d2]
__device__ __half   g_est[2][F_ * B_ * D_];  // ping-pong estimates, [f][b][d]
__device__ __half   g_ne[F_ * B_ * D_];      // unbound estimates, [f][b][d]
__device__ __half   g_inp[B_ * D_];          // input +-1
__device__ int      g_diff[ITERS_];
__device__ int      g_amax[B_ * F_];
__device__ unsigned g_count;

__device__ __forceinline__ __half sgnh(float x) {
    return __float2half(x >= 0.f ? 1.f : -1.f);
}

__device__ __forceinline__ void mma16816(float* c, const unsigned* a, unsigned b0, unsigned b1) {
    asm volatile(
        "mma.sync.aligned.m16n8k16.row.col.f32.f16.f16.f32 "
        "{%0,%1,%2,%3}, {%4,%5,%6,%7}, {%8,%9}, {%0,%1,%2,%3};\n"
        : "+f"(c[0]), "+f"(c[1]), "+f"(c[2]), "+f"(c[3])
        : "r"(a[0]), "r"(a[1]), "r"(a[2]), "r"(a[3]), "r"(b0), "r"(b1));
}

__device__ __forceinline__ void imma16832(int* c, const unsigned* a, unsigned b0, unsigned b1) {
    asm volatile(
        "mma.sync.aligned.m16n8k32.row.col.s32.s8.s8.s32 "
        "{%0,%1,%2,%3}, {%4,%5,%6,%7}, {%8,%9}, {%0,%1,%2,%3};\n"
        : "+r"(c[0]), "+r"(c[1]), "+r"(c[2]), "+r"(c[3])
        : "r"(a[0]), "r"(a[1]), "r"(a[2]), "r"(a[3]), "r"(b0), "r"(b1));
}

__device__ __forceinline__ void ldsm4(unsigned& r0, unsigned& r1, unsigned& r2, unsigned& r3,
                                      unsigned addr) {
    asm volatile("ldmatrix.sync.aligned.m8n8.x4.shared.b16 {%0,%1,%2,%3}, [%4];\n"
                 : "=r"(r0), "=r"(r1), "=r"(r2), "=r"(r3)
                 : "r"(addr));
}

__device__ __forceinline__ unsigned sptr(const void* p) {
    return (unsigned)__cvta_generic_to_shared(p);
}

#define CP_ASYNC16(s, g) \
    asm volatile("cp.async.ca.shared.global [%0], [%1], 16;\n" ::"r"(s), "l"(g))
#define CP_COMMIT asm volatile("cp.async.commit_group;\n")
#define CP_WAIT(n) asm volatile("cp.async.wait_group %0;\n" ::"n"(n))

#define STS128(addr, r0, r1, r2, r3) \
    asm volatile("st.shared.v4.b32 [%0], {%1, %2, %3, %4};\n" ::"r"(addr), "r"(r0), "r"(r1), \
                 "r"(r2), "r"(r3) : "memory")

// software global barrier (1 CTA/SM co-residency; thread0 fence flushes L1D)
__device__ __forceinline__ void gbar(unsigned target) {
    __syncthreads();
    if (threadIdx.x == 0) {
        __threadfence();
        atomicAdd(&g_count, 1u);
        while (*((volatile unsigned*)&g_count) < target) {}
        __threadfence();
    }
    __syncthreads();
}

// ---------------- prep ----------------
__global__ __launch_bounds__(256) void k_prep(const float4* cb, const float* inp, const float* ie) {
    int tid = blockIdx.x * blockDim.x + threadIdx.x;
    int stride = gridDim.x * blockDim.x;
    const int n = F_ * M_ * D_ / 4;
    __half2* outc = reinterpret_cast<__half2*>(g_Ch);
    for (int i = tid; i < n; i += stride) {
        float4 v = cb[i];
        outc[2 * i] = __halves2half2(sgnh(v.x), sgnh(v.y));
        outc[2 * i + 1] = __halves2half2(sgnh(v.z), sgnh(v.w));
    }
    for (int i = tid; i < B_ * D_; i += stride) g_inp[i] = sgnh(inp[i]);
    for (int i = tid; i < B_ * F_ * D_; i += stride) {
        int b = i / (F_ * D_);
        int f = (i / D_) % F_;
        int d = i % D_;
        g_est[0][(f * B_ + b) * D_ + d] = sgnh(ie[i]);
    }
    if (tid < ITERS_) g_diff[tid] = 0;
    if (tid == 0) g_count = 0;
    for (int i = tid; i < B_ * F_; i += stride) g_amax[i] = -1;
}

// ---------------- bitpack: g_Cb[f][d][w], bit j = signbit(C[f][w*32+j][d]) ----------------
__global__ __launch_bounds__(256) void k_pack() {
    const int gw = (blockIdx.x * 256 + threadIdx.x) >> 5;  // 0..511
    const int lane = threadIdx.x & 31;
    const int f = gw >> 7, w = gw & 127;
    const __half* src = g_Ch + ((size_t)f * M_ + (size_t)w * 32 + lane) * D_;
    unsigned* dst = g_Cb + (size_t)f * D_ * 128 + w;
    for (int d0 = 0; d0 < D_; d0 += 8) {
        uint4 v = *(const uint4*)(src + d0);
        unsigned b[4] = {v.x, v.y, v.z, v.w};
#pragma unroll
        for (int q = 0; q < 4; q++) {
            unsigned lo = __ballot_sync(0xffffffffu, (b[q] >> 15) & 1u);
            unsigned hi = __ballot_sync(0xffffffffu, b[q] >> 31);
            if (lane == 2 * q) dst[(size_t)(d0 + 2 * q) * 128] = lo;
            if (lane == 2 * q + 1) dst[(size_t)(d0 + 2 * q + 1) * 128] = hi;
        }
    }
}

// expand one 32-bit sign word into 32 int8 bytes (+1 / -1)
// FIX vs R14: per-byte select via XOR (0x01^0xFE=0xFF); the old
// `0x01010101 - (sp<<1)` borrowed across byte lanes and corrupted bytes.
__device__ __forceinline__ void expand32(unsigned W, unsigned out[8]) {
#pragma unroll
    for (int nib = 0; nib < 8; nib++) {
        unsigned sp = (((W >> (4 * nib)) & 0xFu) * 0x00204081u) & 0x01010101u;
        out[nib] = 0x01010101u ^ (sp * 0xFEu);  // bit=0 -> 0x01 (+1), bit=1 -> 0xFF (-1)
    }
}

// ---------------- Gram via int8 IMMA from bitpacked loads ----------------
// grid (36, 4): upper-tri 128x128 tiles + mirror. K=4096, chunks of 128, 2-buffer,
// loads = 16B bitpacked LDG per chunk per thread, in-register expand, STS.
#define G4_PAD 144
#define G4_BUFB (128 * G4_PAD)          // 18432 B per stage per operand
#define G4_SMEM (4 * G4_BUFB)           // 2 stages x (A+B) = 73728 B
__global__ __launch_bounds__(256) void k_gram4() {
    extern __shared__ __align__(16) char dsm[];
    int idx = blockIdx.x;
    const int f = blockIdx.y;
    int ti = 0;
    while (idx >= 8 - ti) { idx -= 8 - ti; ti++; }
    const int tj = ti + idx;
    const int d1b = ti * 128, d2b = tj * 128;
    const int tid = threadIdx.x, lane = tid & 31, w = tid >> 5;
    const int wm = w >> 2, wn = w & 3;  // 2 x 4 warps
    const int mr = wm * 64, nc = wn * 32;

    const unsigned SAb = sptr(dsm);            // [2][128][144]
    const unsigned SBb = SAb + 2 * G4_BUFB;    // [2][128][144]

    int acc[4][4][4];
#pragma unroll
    for (int i = 0; i < 4; i++)
#pragma unroll
        for (int j = 0; j < 4; j++)
#pragma unroll
            for (int q = 0; q < 4; q++) acc[i][j][q] = 0;

    const int r = tid & 127, op = tid >> 7;  // 128 threads fill A rows, 128 fill B rows
    const int grow = (op ? d2b : d1b) + r;
    const unsigned* bsrc = g_Cb + (size_t)(f * D_ + grow) * 128;
    const unsigned mybase = (op ? SBb : SAb) + r * G4_PAD;

    // expand 4 words (one 128-K chunk) into smem row
    auto expand_sts = [&](uint4 cw, int buf) {
        unsigned sb = mybase + buf * G4_BUFB;
        unsigned wv[4] = {cw.x, cw.y, cw.z, cw.w};
#pragma unroll
        for (int wi = 0; wi < 4; wi++) {
            unsigned o[8];
            expand32(wv[wi], o);
            STS128(sb + wi * 32, o[0], o[1], o[2], o[3]);
            STS128(sb + wi * 32 + 16, o[4], o[5], o[6], o[7]);
        }
    };

    const int NCH = M_ / 128;  // 32 chunks
    uint4 cur = *(const uint4*)(bsrc);
    expand_sts(cur, 0);
    uint4 nxt = *(const uint4*)(bsrc + 4);
    __syncthreads();

    for (int c = 0; c < NCH; c++) {
        const unsigned abuf = SAb + (c & 1) * G4_BUFB;
        const unsigned bbuf = SBb + (c & 1) * G4_BUFB;
#pragma unroll
        for (int ks = 0; ks < 4; ks++) {
            const int mg = lane >> 3, lr = lane & 7;
            unsigned a[4][4], bb[4][2];
            const int rowA = ((mg & 1) ? 8 : 0) + lr;
            const int bofA = ks * 32 + ((mg & 2) ? 16 : 0);
#pragma unroll
            for (int i = 0; i < 4; i++)
                ldsm4(a[i][0], a[i][1], a[i][2], a[i][3],
                      abuf + (mr + i * 16 + rowA) * G4_PAD + bofA);
            const int rowB = ((mg & 2) ? 8 : 0) + lr;
            const int bofB = ks * 32 + ((mg & 1) ? 16 : 0);
#pragma unroll
            for (int jp = 0; jp < 2; jp++) {
                unsigned r0, r1, r2, r3;
                ldsm4(r0, r1, r2, r3, bbuf + (nc + jp * 16 + rowB) * G4_PAD + bofB);
                bb[jp * 2][0] = r0; bb[jp * 2][1] = r1;
                bb[jp * 2 + 1][0] = r2; bb[jp * 2 + 1][1] = r3;
            }
#pragma unroll
            for (int i = 0; i < 4; i++)
#pragma unroll
                for (int j = 0; j < 4; j++) imma16832(acc[i][j], a[i], bb[j][0], bb[j][1]);
        }
        if (c + 1 < NCH) {
            expand_sts(nxt, (c + 1) & 1);
            if (c + 2 < NCH) nxt = *(const uint4*)(bsrc + (size_t)(c + 2) * 4);
        }
        __syncthreads();
    }

    // epilogue: G = acc/2 (exact in fp16), mirror for off-diagonal tiles
    __half* G = g_G + (size_t)f * D_ * D_;
#pragma unroll
    for (int i = 0; i < 4; i++) {
        const int r0 = d1b + mr + i * 16 + (lane >> 2);
        const int r1 = r0 + 8;
#pragma unroll
        for (int j = 0; j < 4; j++) {
            const int c0 = d2b + nc + j * 8 + (lane & 3) * 2;
            __half h0 = __float2half((float)acc[i][j][0] * 0.5f);
            __half h1 = __float2half((float)acc[i][j][1] * 0.5f);
            __half h2 = __float2half((float)acc[i][j][2] * 0.5f);
            __half h3 = __float2half((float)acc[i][j][3] * 0.5f);
            *(__half2*)(G + (size_t)r0 * D_ + c0) = __halves2half2(h0, h1);
            *(__half2*)(G + (size_t)r1 * D_ + c0) = __halves2half2(h2, h3);
            if (ti != tj) {
                G[(size_t)c0 * D_ + r0] = h0;
                G[(size_t)(c0 + 1) * D_ + r0] = h1;
                G[(size_t)c0 * D_ + r1] = h2;
                G[(size_t)(c0 + 1) * D_ + r1] = h3;
            }
        }
    }
}

// ---------------- persistent mega-kernel ----------------
// cta = bq(2) x dt(16) x f(4): phase-B tile 32b x 64d; G slice 64x1024 smem-resident.
// smem: GS [64][1032] halves = 132096 B; NE ring [4][32][136] halves = 34816 B.
// cleanup overlays the same buffer.
#define GS_STRIDE 1032
#define NE_STRIDE 136
#define NE_BUFH (32 * NE_STRIDE)
#define MG_SMEM (132096 + 4 * NE_BUFH * 2)

__device__ __forceinline__ unsigned packsign(float x, float y) {
    return (x >= 0.f ? 0x3C00u : 0xBC00u) | ((y >= 0.f ? 0x3C00u : 0xBC00u) << 16);
}

__global__ __launch_bounds__(256) void k_mega(float* out, int out_size) {
    extern __shared__ __align__(16) char dsm[];
    const unsigned GsA = sptr(dsm);
    const unsigned NEA = GsA + 132096;

    const int tid = threadIdx.x, lane = tid & 31, w = tid >> 5;
    const int cta = blockIdx.x;
    const int f_l = cta & 3;
    const int dt = (cta >> 2) & 15;
    const int bq = cta >> 6;            // 0..1
    const int d1b = dt * 64;
    const int b0 = bq * 32;
    const int wm = w & 1, wn = w >> 1;  // 2 b-halves x 4 d-quarters

    const int er = b0 + wm * 16 + (lane >> 2);
    const int ec = d1b + wn * 16 + (lane & 3) * 2;

    unsigned prev[4];
    {
        const __half* e0 = g_est[0] + (size_t)f_l * B_ * D_;
        prev[0] = *(const unsigned*)(e0 + (size_t)er * D_ + ec);
        prev[1] = *(const unsigned*)(e0 + (size_t)(er + 8) * D_ + ec);
        prev[2] = *(const unsigned*)(e0 + (size_t)er * D_ + ec + 8);
        prev[3] = *(const unsigned*)(e0 + (size_t)(er + 8) * D_ + ec + 8);
    }

    // ---- load resident G slice (64 rows x 1024) once ----
    {
        const __half* Gg = g_G + (size_t)f_l * D_ * D_;
        const int row = tid >> 2;            // 0..63
        const int so = (tid & 3) * 256;      // halves
        const __half* src = Gg + (size_t)(d1b + row) * D_ + so;
        const unsigned dstb = GsA + (row * GS_STRIDE + so) * 2;
#pragma unroll
        for (int j = 0; j < 32; j++) CP_ASYNC16(dstb + j * 16, src + j * 8);
        CP_COMMIT;
        CP_WAIT(0);
        __syncthreads();
    }

    unsigned phase = 0;
    int cur = 0;

    for (int it = 0; it < ITERS_; ++it) {
        // ---- phase A: XOR unbind ----
        {
            const unsigned* inp2 = (const unsigned*)g_inp;
            const unsigned* e = (const unsigned*)g_est[cur];
            unsigned* ne = (unsigned*)g_ne;
            const int i = cta * 256 + tid;  // exactly NHALF_ threads
            unsigned a0 = e[i], a1 = e[NHALF_ + i], a2 = e[2 * NHALF_ + i], a3 = e[3 * NHALF_ + i];
            unsigned X = inp2[i] ^ a0 ^ a1 ^ a2 ^ a3;
            ne[i] = X ^ a0 ^ 0x3C003C00u;
            ne[NHALF_ + i] = X ^ a1 ^ 0x3C003C00u;
            ne[2 * NHALF_ + i] = X ^ a2 ^ 0x3C003C00u;
            ne[3 * NHALF_ + i] = X ^ a3 ^ 0x3C003C00u;
        }
        phase++; gbar(NCTA_ * phase);

        // ---- phase B: upd = sign(G @ ne); 32b x 64d; ne 4-stage ring, G resident ----
        {
            float acc0[4] = {0.f, 0.f, 0.f, 0.f};
            float acc1[4] = {0.f, 0.f, 0.f, 0.f};
            const __half* NEg = g_ne + (size_t)f_l * B_ * D_ + (size_t)b0 * D_;
            const int lb = tid >> 3, so2 = (tid & 7) * 16;  // 32 rows x 8 x 16-half segs

#define PB_ISSUE(cc)                                                                    \
    do {                                                                                \
        unsigned db = NEA + (((cc) & 3) * NE_BUFH + lb * NE_STRIDE + so2) * 2;          \
        const __half* s = NEg + (size_t)lb * D_ + (cc) * 128 + so2;                     \
        CP_ASYNC16(db, s);                                                              \
        CP_ASYNC16(db + 16, s + 8);                                                     \
        CP_COMMIT;                                                                      \
    } while (0)

            PB_ISSUE(0); PB_ISSUE(1); PB_ISSUE(2);
            for (int c = 0; c < 8; c++) {
                CP_WAIT(2);
                __syncthreads();
                const unsigned nb = NEA + ((c & 3) * NE_BUFH) * 2;
#pragma unroll
                for (int ks = 0; ks < 8; ks++) {
                    const int rowA = wm * 16 + (lane & 15);
                    const int colh = ks * 16 + (lane >> 4) * 8;
                    unsigned a[4];
                    ldsm4(a[0], a[1], a[2], a[3], nb + (rowA * NE_STRIDE + colh) * 2);
                    const int rowB = wn * 16 + (lane & 15);
                    unsigned b0r, b1r, b2r, b3r;
                    ldsm4(b0r, b1r, b2r, b3r,
                          GsA + (rowB * GS_STRIDE + c * 128 + colh) * 2);
                    mma16816(acc0, a, b0r, b2r);
                    mma16816(acc1, a, b1r, b3r);
                }
                if (c + 3 < 8) { PB_ISSUE(c + 3); } else { CP_COMMIT; }
            }
#undef PB_ISSUE

            __half* enew = g_est[cur ^ 1] + (size_t)f_l * B_ * D_;
            unsigned s[4];
            s[0] = packsign(acc0[0], acc0[1]);
            s[1] = packsign(acc0[2], acc0[3]);
            s[2] = packsign(acc1[0], acc1[1]);
            s[3] = packsign(acc1[2], acc1[3]);
            *(unsigned*)(enew + (size_t)er * D_ + ec) = s[0];
            *(unsigned*)(enew + (size_t)(er + 8) * D_ + ec) = s[1];
            *(unsigned*)(enew + (size_t)er * D_ + ec + 8) = s[2];
            *(unsigned*)(enew + (size_t)(er + 8) * D_ + ec + 8) = s[3];
            bool changed = (s[0] != prev[0]) | (s[1] != prev[1]) | (s[2] != prev[2]) |
                           (s[3] != prev[3]);
            prev[0] = s[0]; prev[1] = s[1]; prev[2] = s[2]; prev[3] = s[3];
            unsigned mask = __ballot_sync(0xffffffffu, changed);
            if (lane == 0 && mask) atomicOr(&g_diff[it], 1);
        }
        phase++; gbar(NCTA_ * phase);
        int ch = g_diff[it];
        cur ^= 1;
        if (ch == 0) break;  // fixed point: remaining iterations are no-ops
    }

    // ---- cleanup: sim = est @ C^T, 64b x 128m, 3-stage pipeline (overlays dsm) ----
    {
        const unsigned cAa = GsA;            // [3][64][40] halves
        const unsigned cBa = GsA + 15360;    // [3][128][40] halves
        const int fc = f_l;
        const int mtb = (cta >> 2) * 128;    // (bq<<4)|dt covers 0..31 uniquely
        const int wbC = w & 3, wd2 = w >> 2;
        float acc[8][4];
#pragma unroll
        for (int j = 0; j < 8; j++)
#pragma unroll
            for (int q = 0; q < 4; q++) acc[j][q] = 0.f;

        const __half* A = g_est[cur] + (size_t)fc * B_ * D_;
        const __half* C = g_Ch + (size_t)fc * M_ * D_;
        const int lb = tid >> 2, seg = (tid & 3) * 8;
        const int rb2 = tid >> 1, segb = (tid & 1) * 16;

#define CL_ISSUE(cc)                                                                     \
    do {                                                                                 \
        CP_ASYNC16(cAa + (((cc) % 3) * 2560 + lb * 40 + seg) * 2,                        \
                   A + (size_t)lb * D_ + (cc) * 32 + seg);                               \
        CP_ASYNC16(cBa + (((cc) % 3) * 5120 + rb2 * 40 + segb) * 2,                      \
                   C + (size_t)(mtb + rb2) * D_ + (cc) * 32 + segb);                     \
        CP_ASYNC16(cBa + (((cc) % 3) * 5120 + rb2 * 40 + segb + 8) * 2,                  \
                   C + (size_t)(mtb + rb2) * D_ + (cc) * 32 + segb + 8);                 \
        CP_COMMIT;                                                                       \
    } while (0)

        CL_ISSUE(0); CL_ISSUE(1);
        for (int c = 0; c < 32; c++) {
            CP_WAIT(1);
            __syncthreads();
            const unsigned ab = cAa + ((c % 3) * 2560) * 2;
            const unsigned bbf = cBa + ((c % 3) * 5120) * 2;
#pragma unroll
            for (int ks = 0; ks < 2; ks++) {
                const int rowA = wbC * 16 + (lane & 15);
                const int colh = ks * 16 + (lane >> 4) * 8;
                unsigned a[4];
                ldsm4(a[0], a[1], a[2], a[3], ab + (rowA * 40 + colh) * 2);
#pragma unroll
                for (int jj = 0; jj < 4; jj++) {
                    const int rowB = wd2 * 64 + jj * 16 + (lane & 15);
                    unsigned b0r, b1r, b2r, b3r;
                    ldsm4(b0r, b1r, b2r, b3r, bbf + (rowB * 40 + colh) * 2);
                    mma16816(acc[2 * jj], a, b0r, b2r);
                    mma16816(acc[2 * jj + 1], a, b1r, b3r);
                }
            }
            if (c + 2 < 32) { CL_ISSUE(c + 2); } else { CP_COMMIT; }
        }
#undef CL_ISSUE

        const int erC = wbC * 16 + (lane >> 2);
        int best0 = -1, best1 = -1;
#pragma unroll
        for (int jj = 0; jj < 4; jj++) {
#pragma unroll
            for (int t = 0; t < 2; t++) {
                const int m0 = mtb + wd2 * 64 + jj * 16 + t * 8 + (lane & 3) * 2;
                const float* ac = acc[2 * jj + t];
#pragma unroll
                for (int q = 0; q < 2; q++) {
                    best0 = max(best0, (((int)fabsf(ac[q])) << 12) | (4095 - (m0 + q)));
                    best1 = max(best1, (((int)fabsf(ac[2 + q])) << 12) | (4095 - (m0 + q)));
                }
            }
        }
        atomicMax(&g_amax[erC * F_ + fc], best0);
        atomicMax(&g_amax[(erC + 8) * F_ + fc], best1);
    }
    phase++; gbar(NCTA_ * phase);

    // ---- final outputs: [outcome(256)] [est(262144)] [iters] [conv] ----
    {
        const int g = cta * 256 + tid, gs = NCTA_ * 256;
        for (int i = g; i < B_ * F_; i += gs)
            if (i < out_size) out[i] = (float)(4095 - (g_amax[i] & 4095));
        for (int i = g; i < B_ * F_ * D_; i += gs) {
            int o = B_ * F_ + i;
            if (o < out_size) {
                int b = i / (F_ * D_);
                int f = (i / D_) % F_;
                int d = i % D_;
                out[o] = __half2float(g_est[cur][(f * B_ + b) * D_ + d]);
            }
        }
        if (cta == 0 && tid == 0) {
            int iters = 0, conv = 0;
            for (int i = 0; i < ITERS_; i++) {
                if (!conv) iters++;
                if (g_diff[i] == 0) conv = 1;
            }
            int o = B_ * F_ + B_ * F_ * D_;
            if (o < out_size) out[o] = (float)iters;
            if (o + 1 < out_size) out[o + 1] = (float)conv;
        }
    }
}

extern "C" void kernel_launch(void* const* d_in, const int* in_sizes, int n_in,
                              void* d_out, int out_size) {
    const float* inp = (const float*)d_in[0];
    const float* ie  = (const float*)d_in[1];
    const float* cb  = (const float*)d_in[2];

    cudaFuncSetAttribute(k_gram4, cudaFuncAttributeMaxDynamicSharedMemorySize, G4_SMEM);
    cudaFuncSetAttribute(k_mega, cudaFuncAttributeMaxDynamicSharedMemorySize, MG_SMEM);

    k_prep<<<1024, 256>>>((const float4*)cb, inp, ie);
    k_pack<<<64, 256>>>();
    k_gram4<<<dim3(36, 4), 256, G4_SMEM>>>();
    k_mega<<<NCTA_, 256, MG_SMEM>>>((float*)d_out, out_size);
}

// round 16
// speedup vs baseline: 1.0698x; 1.0698x over previous
#include <cuda_runtime.h>
#include <cuda_fp16.h>
#include <cstdint>

#define B_ 64
#define F_ 4
#define M_ 4096
#define D_ 1024
#define ITERS_ 15
#define NCTA_ 128
#define NHALF_ (B_ * D_ / 2)

// ---------------- device scratch ----------------
__device__ __half   g_Ch[F_ * M_ * D_];      // codebooks fp16 +-1, [f][m][d]
__device__ int8_t   g_Cti[F_ * D_ * M_];     // transposed int8 codebooks, [f][d][m]
__device__ __half   g_G[F_ * D_ * D_];       // (C^T C)/2 fp16, [f][d1][d2]
__device__ __half   g_est[2][F_ * B_ * D_];  // ping-pong estimates, [f][b][d]
__device__ __half   g_inp[B_ * D_];          // input +-1
__device__ int      g_diff[ITERS_];
__device__ int      g_amax[B_ * F_];
__device__ unsigned g_count;

__device__ __forceinline__ __half sgnh(float x) {
    return __float2half(x >= 0.f ? 1.f : -1.f);
}

__device__ __forceinline__ void mma16816(float* c, const unsigned* a, unsigned b0, unsigned b1) {
    asm volatile(
        "mma.sync.aligned.m16n8k16.row.col.f32.f16.f16.f32 "
        "{%0,%1,%2,%3}, {%4,%5,%6,%7}, {%8,%9}, {%0,%1,%2,%3};\n"
        : "+f"(c[0]), "+f"(c[1]), "+f"(c[2]), "+f"(c[3])
        : "r"(a[0]), "r"(a[1]), "r"(a[2]), "r"(a[3]), "r"(b0), "r"(b1));
}

__device__ __forceinline__ void imma16832(int* c, const unsigned* a, unsigned b0, unsigned b1) {
    asm volatile(
        "mma.sync.aligned.m16n8k32.row.col.s32.s8.s8.s32 "
        "{%0,%1,%2,%3}, {%4,%5,%6,%7}, {%8,%9}, {%0,%1,%2,%3};\n"
        : "+r"(c[0]), "+r"(c[1]), "+r"(c[2]), "+r"(c[3])
        : "r"(a[0]), "r"(a[1]), "r"(a[2]), "r"(a[3]), "r"(b0), "r"(b1));
}

__device__ __forceinline__ void ldsm4(unsigned& r0, unsigned& r1, unsigned& r2, unsigned& r3,
                                      unsigned addr) {
    asm volatile("ldmatrix.sync.aligned.m8n8.x4.shared.b16 {%0,%1,%2,%3}, [%4];\n"
                 : "=r"(r0), "=r"(r1), "=r"(r2), "=r"(r3)
                 : "r"(addr));
}

__device__ __forceinline__ unsigned sptr(const void* p) {
    return (unsigned)__cvta_generic_to_shared(p);
}

#define CP_ASYNC16(s, g) \
    asm volatile("cp.async.ca.shared.global [%0], [%1], 16;\n" ::"r"(s), "l"(g))
#define CP_COMMIT asm volatile("cp.async.commit_group;\n")
#define CP_WAIT(n) asm volatile("cp.async.wait_group %0;\n" ::"n"(n))

#define STS128(addr, r0, r1, r2, r3) \
    asm volatile("st.shared.v4.b32 [%0], {%1, %2, %3, %4};\n" ::"r"(addr), "r"(r0), "r"(r1), \
                 "r"(r2), "r"(r3) : "memory")

// software global barrier (1 CTA/SM co-residency; thread0 fence flushes L1D)
__device__ __forceinline__ void gbar(unsigned target) {
    __syncthreads();
    if (threadIdx.x == 0) {
        __threadfence();
        atomicAdd(&g_count, 1u);
        while (*((volatile unsigned*)&g_count) < target) {}
        __threadfence();
    }
    __syncthreads();
}

// ---------------- prep ----------------
__global__ __launch_bounds__(256) void k_prep(const float4* cb, const float* inp, const float* ie) {
    int tid = blockIdx.x * blockDim.x + threadIdx.x;
    int stride = gridDim.x * blockDim.x;
    const int n = F_ * M_ * D_ / 4;
    __half2* outc = reinterpret_cast<__half2*>(g_Ch);
    for (int i = tid; i < n; i += stride) {
        float4 v = cb[i];
        outc[2 * i] = __halves2half2(sgnh(v.x), sgnh(v.y));
        outc[2 * i + 1] = __halves2half2(sgnh(v.z), sgnh(v.w));
    }
    for (int i = tid; i < B_ * D_; i += stride) g_inp[i] = sgnh(inp[i]);
    for (int i = tid; i < B_ * F_ * D_; i += stride) {
        int b = i / (F_ * D_);
        int f = (i / D_) % F_;
        int d = i % D_;
        g_est[0][(f * B_ + b) * D_ + d] = sgnh(ie[i]);
    }
    if (tid < ITERS_) g_diff[tid] = 0;
    if (tid == 0) g_count = 0;
    for (int i = tid; i < B_ * F_; i += stride) g_amax[i] = -1;
}

// ---------------- transpose + int8: Cti[f][d][m] = sign8(Ch[f][m][d]) ----------------
__global__ __launch_bounds__(256) void k_trans8() {
    __shared__ __half T[64][72];
    const int mt = blockIdx.x * 64, dt = blockIdx.y * 64, f = blockIdx.z;
    const int tid = threadIdx.x;
    const __half* src = g_Ch + (size_t)f * M_ * D_;
    int8_t* dst = g_Cti + (size_t)f * D_ * M_;
#pragma unroll
    for (int q = 0; q < 2; q++) {
        int o = tid * 2 + q;
        int r = o >> 3, seg = o & 7;
        *(uint4*)&T[r][seg * 8] = *(const uint4*)(src + (size_t)(mt + r) * D_ + dt + seg * 8);
    }
    __syncthreads();
#pragma unroll
    for (int q = 0; q < 2; q++) {
        int o = tid * 2 + q;
        int r = o >> 3, seg = o & 7;
        int8_t tmp[8];
#pragma unroll
        for (int j = 0; j < 8; j++)
            tmp[j] = (__half_as_ushort(T[seg * 8 + j][r]) & 0x8000) ? (int8_t)-1 : (int8_t)1;
        *(uint2*)(dst + (size_t)(dt + r) * M_ + mt + seg * 8) = *(uint2*)tmp;
    }
}

// ---------------- Gram via int8 IMMA (proven R11 version) ----------------
// grid (36, 4): upper-tri 128x128 tiles + mirror. K=4096, chunks of 128, 4-buffer ring.
#define G3_PAD 144
#define G3_BUFB (128 * G3_PAD)
#define G3_SMEM (8 * G3_BUFB)
__global__ __launch_bounds__(256) void k_gram3() {
    extern __shared__ __align__(16) char dsm[];
    int idx = blockIdx.x;
    const int f = blockIdx.y;
    int ti = 0;
    while (idx >= 8 - ti) { idx -= 8 - ti; ti++; }
    const int tj = ti + idx;
    const int d1b = ti * 128, d2b = tj * 128;
    const int8_t* Ct = g_Cti + (size_t)f * D_ * M_;
    const int tid = threadIdx.x, lane = tid & 31, w = tid >> 5;
    const int wm = w >> 2, wn = w & 3;
    const int mr = wm * 64, nc = wn * 32;

    const unsigned SAb = sptr(dsm);
    const unsigned SBb = SAb + 4 * G3_BUFB;

    int acc[4][4][4];
#pragma unroll
    for (int i = 0; i < 4; i++)
#pragma unroll
        for (int j = 0; j < 4; j++)
#pragma unroll
            for (int q = 0; q < 4; q++) acc[i][j][q] = 0;

    const int r = tid & 127, op = tid >> 7;
    const int grow = (op ? d2b : d1b) + r;
    const int8_t* srcrow = Ct + (size_t)grow * M_;
    const unsigned mybase = (op ? SBb : SAb) + r * G3_PAD;

#define G3_LOAD(cc)                                                   \
    do {                                                              \
        unsigned sb = mybase + ((cc) & 3) * G3_BUFB;                  \
        const int8_t* s = srcrow + (size_t)(cc) * 128;                \
        _Pragma("unroll") for (int q8 = 0; q8 < 8; q8++)              \
            CP_ASYNC16(sb + q8 * 16, s + q8 * 16);                    \
        CP_COMMIT;                                                    \
    } while (0)

    G3_LOAD(0); G3_LOAD(1); G3_LOAD(2);
    const int NCH = M_ / 128;
    for (int c = 0; c < NCH; c++) {
        CP_WAIT(2);
        __syncthreads();
        const unsigned abuf = SAb + (c & 3) * G3_BUFB;
        const unsigned bbuf = SBb + (c & 3) * G3_BUFB;
#pragma unroll
        for (int ks = 0; ks < 4; ks++) {
            const int mg = lane >> 3, lr = lane & 7;
            unsigned a[4][4], bb[4][2];
            const int rowA = ((mg & 1) ? 8 : 0) + lr;
            const int bofA = ks * 32 + ((mg & 2) ? 16 : 0);
#pragma unroll
            for (int i = 0; i < 4; i++)
                ldsm4(a[i][0], a[i][1], a[i][2], a[i][3],
                      abuf + (mr + i * 16 + rowA) * G3_PAD + bofA);
            const int rowB = ((mg & 2) ? 8 : 0) + lr;
            const int bofB = ks * 32 + ((mg & 1) ? 16 : 0);
#pragma unroll
            for (int jp = 0; jp < 2; jp++) {
                unsigned r0, r1, r2, r3;
                ldsm4(r0, r1, r2, r3, bbuf + (nc + jp * 16 + rowB) * G3_PAD + bofB);
                bb[jp * 2][0] = r0; bb[jp * 2][1] = r1;
                bb[jp * 2 + 1][0] = r2; bb[jp * 2 + 1][1] = r3;
            }
#pragma unroll
            for (int i = 0; i < 4; i++)
#pragma unroll
                for (int j = 0; j < 4; j++) imma16832(acc[i][j], a[i], bb[j][0], bb[j][1]);
        }
        if (c + 3 < NCH) { G3_LOAD(c + 3); } else { CP_COMMIT; }
    }
#undef G3_LOAD

    __half* G = g_G + (size_t)f * D_ * D_;
#pragma unroll
    for (int i = 0; i < 4; i++) {
        const int r0 = d1b + mr + i * 16 + (lane >> 2);
        const int r1 = r0 + 8;
#pragma unroll
        for (int j = 0; j < 4; j++) {
            const int c0 = d2b + nc + j * 8 + (lane & 3) * 2;
            __half h0 = __float2half((float)acc[i][j][0] * 0.5f);
            __half h1 = __float2half((float)acc[i][j][1] * 0.5f);
            __half h2 = __float2half((float)acc[i][j][2] * 0.5f);
            __half h3 = __float2half((float)acc[i][j][3] * 0.5f);
            *(__half2*)(G + (size_t)r0 * D_ + c0) = __halves2half2(h0, h1);
            *(__half2*)(G + (size_t)r1 * D_ + c0) = __halves2half2(h2, h3);
            if (ti != tj) {
                G[(size_t)c0 * D_ + r0] = h0;
                G[(size_t)(c0 + 1) * D_ + r0] = h1;
                G[(size_t)c0 * D_ + r1] = h2;
                G[(size_t)(c0 + 1) * D_ + r1] = h3;
            }
        }
    }
}

// ---------------- persistent mega-kernel ----------------
// cta = bq(2) x dt(16) x f(4): tile 32b x 64d; G slice 64x1024 smem-resident.
// Fused unbind: per K-chunk, ne tile computed in-CTA from est via LDG+XOR+STS.
// ONE global barrier per iteration.
#define GS_STRIDE 1032
#define NE_STRIDE 136
#define NE_BUFH (32 * NE_STRIDE)
#define MG_SMEM (132096 + 2 * NE_BUFH * 2)   // 149504 B

__device__ __forceinline__ unsigned packsign(float x, float y) {
    return (x >= 0.f ? 0x3C00u : 0xBC00u) | ((y >= 0.f ? 0x3C00u : 0xBC00u) << 16);
}

__global__ __launch_bounds__(256) void k_mega(float* out, int out_size) {
    extern __shared__ __align__(16) char dsm[];
    const unsigned GsA = sptr(dsm);
    const unsigned NEA = GsA + 132096;

    const int tid = threadIdx.x, lane = tid & 31, w = tid >> 5;
    const int cta = blockIdx.x;
    const int f_l = cta & 3;
    const int dt = (cta >> 2) & 15;
    const int bq = cta >> 6;
    const int d1b = dt * 64;
    const int b0 = bq * 32;
    const int wm = w & 1, wn = w >> 1;

    const int er = b0 + wm * 16 + (lane >> 2);
    const int ec = d1b + wn * 16 + (lane & 3) * 2;

    // the three factors != f_l (for the unbind XOR)
    const int fa = (f_l + 1) & 3, fb = (f_l + 2) & 3, fc3 = (f_l + 3) & 3;

    unsigned prev[4];
    {
        const __half* e0 = g_est[0] + (size_t)f_l * B_ * D_;
        prev[0] = *(const unsigned*)(e0 + (size_t)er * D_ + ec);
        prev[1] = *(const unsigned*)(e0 + (size_t)(er + 8) * D_ + ec);
        prev[2] = *(const unsigned*)(e0 + (size_t)er * D_ + ec + 8);
        prev[3] = *(const unsigned*)(e0 + (size_t)(er + 8) * D_ + ec + 8);
    }

    // ---- load resident G slice (64 rows x 1024) once ----
    {
        const __half* Gg = g_G + (size_t)f_l * D_ * D_;
        const int row = tid >> 2;
        const int so = (tid & 3) * 256;
        const __half* src = Gg + (size_t)(d1b + row) * D_ + so;
        const unsigned dstb = GsA + (row * GS_STRIDE + so) * 2;
#pragma unroll
        for (int j = 0; j < 32; j++) CP_ASYNC16(dstb + j * 16, src + j * 8);
        CP_COMMIT;
        CP_WAIT(0);
        __syncthreads();
    }

    // per-thread unbind coordinates: 32 rows x (8 x 16-half segs)
    const int lb = tid >> 3, so2 = (tid & 7) * 16;
    const size_t rowoff = (size_t)(b0 + lb) * D_ + so2;

    unsigned phase = 0;
    int cur = 0;

    for (int it = 0; it < ITERS_; ++it) {
        float acc0[4] = {0.f, 0.f, 0.f, 0.f};
        float acc1[4] = {0.f, 0.f, 0.f, 0.f};

        const __half* eb = g_est[cur];
        const uint4* pin = (const uint4*)(g_inp + rowoff);
        const uint4* pea = (const uint4*)(eb + (size_t)fa * B_ * D_ + rowoff);
        const uint4* peb = (const uint4*)(eb + (size_t)fb * B_ * D_ + rowoff);
        const uint4* pec = (const uint4*)(eb + (size_t)fc3 * B_ * D_ + rowoff);

        uint4 ri[2], ra[2], rb[2], rc[2];
#define MG_LOAD(cc)                                                           \
    do {                                                                      \
        const int off = (cc) * 16; /* 128 halves = 16 uint4 per row chunk */  \
        ri[0] = pin[off]; ri[1] = pin[off + 1];                               \
        ra[0] = pea[off]; ra[1] = pea[off + 1];                               \
        rb[0] = peb[off]; rb[1] = peb[off + 1];                               \
        rc[0] = pec[off]; rc[1] = pec[off + 1];                               \
    } while (0)

#define MG_NE_STS(buf)                                                        \
    do {                                                                      \
        const unsigned db = NEA + ((buf)*NE_BUFH + lb * NE_STRIDE + so2) * 2; \
        unsigned o[4];                                                        \
        _Pragma("unroll") for (int v = 0; v < 2; v++) {                       \
            const unsigned* wi = (const unsigned*)&ri[v];                     \
            const unsigned* wa = (const unsigned*)&ra[v];                     \
            const unsigned* wb = (const unsigned*)&rb[v];                     \
            const unsigned* wc = (const unsigned*)&rc[v];                     \
            _Pragma("unroll") for (int j = 0; j < 4; j++)                     \
                o[j] = wi[j] ^ wa[j] ^ wb[j] ^ wc[j] ^ 0x3C003C00u;           \
            STS128(db + v * 16, o[0], o[1], o[2], o[3]);                      \
        }                                                                     \
    } while (0)

        MG_LOAD(0);
        for (int c = 0; c < 8; c++) {
            MG_NE_STS(c & 1);
            __syncthreads();
            if (c + 1 < 8) MG_LOAD(c + 1);  // LDG latency hidden under mma
            const unsigned nb = NEA + ((c & 1) * NE_BUFH) * 2;
#pragma unroll
            for (int ks = 0; ks < 8; ks++) {
                const int rowA = wm * 16 + (lane & 15);
                const int colh = ks * 16 + (lane >> 4) * 8;
                unsigned a[4];
                ldsm4(a[0], a[1], a[2], a[3], nb + (rowA * NE_STRIDE + colh) * 2);
                const int rowB = wn * 16 + (lane & 15);
                unsigned b0r, b1r, b2r, b3r;
                ldsm4(b0r, b1r, b2r, b3r, GsA + (rowB * GS_STRIDE + c * 128 + colh) * 2);
                mma16816(acc0, a, b0r, b2r);
                mma16816(acc1, a, b1r, b3r);
            }
            __syncthreads();
        }
#undef MG_LOAD
#undef MG_NE_STS

        // epilogue: sign, compare with register prev, store est
        __half* enew = g_est[cur ^ 1] + (size_t)f_l * B_ * D_;
        unsigned s[4];
        s[0] = packsign(acc0[0], acc0[1]);
        s[1] = packsign(acc0[2], acc0[3]);
        s[2] = packsign(acc1[0], acc1[1]);
        s[3] = packsign(acc1[2], acc1[3]);
        *(unsigned*)(enew + (size_t)er * D_ + ec) = s[0];
        *(unsigned*)(enew + (size_t)(er + 8) * D_ + ec) = s[1];
        *(unsigned*)(enew + (size_t)er * D_ + ec + 8) = s[2];
        *(unsigned*)(enew + (size_t)(er + 8) * D_ + ec + 8) = s[3];
        bool changed = (s[0] != prev[0]) | (s[1] != prev[1]) | (s[2] != prev[2]) |
                       (s[3] != prev[3]);
        prev[0] = s[0]; prev[1] = s[1]; prev[2] = s[2]; prev[3] = s[3];
        unsigned mask = __ballot_sync(0xffffffffu, changed);
        if (lane == 0 && mask) atomicOr(&g_diff[it], 1);

        phase++; gbar(NCTA_ * phase);   // single barrier per iteration
        int ch = g_diff[it];
        cur ^= 1;
        if (ch == 0) break;  // fixed point: remaining iterations are no-ops
    }

    // ---- cleanup: sim = est @ C^T, 64b x 128m, 3-stage pipeline (overlays dsm) ----
    {
        const unsigned cAa = GsA;            // [3][64][40] halves
        const unsigned cBa = GsA + 15360;    // [3][128][40] halves
        const int fc = f_l;
        const int mtb = (cta >> 2) * 128;    // (bq<<4)|dt covers 0..31 uniquely
        const int wbC = w & 3, wd2 = w >> 2;
        float acc[8][4];
#pragma unroll
        for (int j = 0; j < 8; j++)
#pragma unroll
            for (int q = 0; q < 4; q++) acc[j][q] = 0.f;

        const __half* A = g_est[cur] + (size_t)fc * B_ * D_;
        const __half* C = g_Ch + (size_t)fc * M_ * D_;
        const int lbc = tid >> 2, seg = (tid & 3) * 8;
        const int rb2 = tid >> 1, segb = (tid & 1) * 16;

#define CL_ISSUE(cc)                                                                     \
    do {                                                                                 \
        CP_ASYNC16(cAa + (((cc) % 3) * 2560 + lbc * 40 + seg) * 2,                       \
                   A + (size_t)lbc * D_ + (cc) * 32 + seg);                              \
        CP_ASYNC16(cBa + (((cc) % 3) * 5120 + rb2 * 40 + segb) * 2,                      \
                   C + (size_t)(mtb + rb2) * D_ + (cc) * 32 + segb);                     \
        CP_ASYNC16(cBa + (((cc) % 3) * 5120 + rb2 * 40 + segb + 8) * 2,                  \
                   C + (size_t)(mtb + rb2) * D_ + (cc) * 32 + segb + 8);                 \
        CP_COMMIT;                                                                       \
    } while (0)

        CL_ISSUE(0); CL_ISSUE(1);
        for (int c = 0; c < 32; c++) {
            CP_WAIT(1);
            __syncthreads();
            const unsigned ab = cAa + ((c % 3) * 2560) * 2;
            const unsigned bbf = cBa + ((c % 3) * 5120) * 2;
#pragma unroll
            for (int ks = 0; ks < 2; ks++) {
                const int rowA = wbC * 16 + (lane & 15);
                const int colh = ks * 16 + (lane >> 4) * 8;
                unsigned a[4];
                ldsm4(a[0], a[1], a[2], a[3], ab + (rowA * 40 + colh) * 2);
#pragma unroll
                for (int jj = 0; jj < 4; jj++) {
                    const int rowB = wd2 * 64 + jj * 16 + (lane & 15);
                    unsigned b0r, b1r, b2r, b3r;
                    ldsm4(b0r, b1r, b2r, b3r, bbf + (rowB * 40 + colh) * 2);
                    mma16816(acc[2 * jj], a, b0r, b2r);
                    mma16816(acc[2 * jj + 1], a, b1r, b3r);
                }
            }
            if (c + 2 < 32) { CL_ISSUE(c + 2); } else { CP_COMMIT; }
        }
#undef CL_ISSUE

        const int erC = wbC * 16 + (lane >> 2);
        int best0 = -1, best1 = -1;
#pragma unroll
        for (int jj = 0; jj < 4; jj++) {
#pragma unroll
            for (int t = 0; t < 2; t++) {
                const int m0 = mtb + wd2 * 64 + jj * 16 + t * 8 + (lane & 3) * 2;
                const float* ac = acc[2 * jj + t];
#pragma unroll
                for (int q = 0; q < 2; q++) {
                    best0 = max(best0, (((int)fabsf(ac[q])) << 12) | (4095 - (m0 + q)));
                    best1 = max(best1, (((int)fabsf(ac[2 + q])) << 12) | (4095 - (m0 + q)));
                }
            }
        }
        atomicMax(&g_amax[erC * F_ + fc], best0);
        atomicMax(&g_amax[(erC + 8) * F_ + fc], best1);
    }
    phase++; gbar(NCTA_ * phase);

    // ---- final outputs: [outcome(256)] [est(262144)] [iters] [conv] ----
    {
        const int g = cta * 256 + tid, gs = NCTA_ * 256;
        for (int i = g; i < B_ * F_; i += gs)
            if (i < out_size) out[i] = (float)(4095 - (g_amax[i] & 4095));
        for (int i = g; i < B_ * F_ * D_; i += gs) {
            int o = B_ * F_ + i;
            if (o < out_size) {
                int b = i / (F_ * D_);
                int f = (i / D_) % F_;
                int d = i % D_;
                out[o] = __half2float(g_est[cur][(f * B_ + b) * D_ + d]);
            }
        }
        if (cta == 0 && tid == 0) {
            int iters = 0, conv = 0;
            for (int i = 0; i < ITERS_; i++) {
                if (!conv) iters++;
                if (g_diff[i] == 0) conv = 1;
            }
            int o = B_ * F_ + B_ * F_ * D_;
            if (o < out_size) out[o] = (float)iters;
            if (o + 1 < out_size) out[o + 1] = (float)conv;
        }
    }
}

extern "C" void kernel_launch(void* const* d_in, const int* in_sizes, int n_in,
                              void* d_out, int out_size) {
    const float* inp = (const float*)d_in[0];
    const float* ie  = (const float*)d_in[1];
    const float* cb  = (const float*)d_in[2];

    cudaFuncSetAttribute(k_gram3, cudaFuncAttributeMaxDynamicSharedMemorySize, G3_SMEM);
    cudaFuncSetAttribute(k_mega, cudaFuncAttributeMaxDynamicSharedMemorySize, MG_SMEM);

    k_prep<<<1024, 256>>>((const float4*)cb, inp, ie);
    k_trans8<<<dim3(M_ / 64, D_ / 64, F_), 256>>>();
    k_gram3<<<dim3(36, 4), 256, G3_SMEM>>>();
    k_mega<<<NCTA_, 256, MG_SMEM>>>((float*)d_out, out_size);
}